// round 1
// baseline (speedup 1.0000x reference)
#include <cuda_runtime.h>
#include <math_constants.h>

// Problem constants (shapes fixed by the dataset)
#define D       64          // feature dim
#define MTOT    1024        // 4*256 test points
#define NTRAIN  4096        // train points
#define TM      64          // test rows per block
#define TN      64          // train cols per smem tile
#define NSPLIT  16          // train chunks across gridDim.y
#define CHUNK   (NTRAIN / NSPLIT)   // 256 train points per block
#define BW      0.04f
#define VARV    (BW * BW)   // 0.0016

// Deterministic partial-sum scratch (no atomics anywhere)
__device__ float g_scratch[NSPLIT * MTOT];

__global__ __launch_bounds__(256, 2)
void kde_partial(const float* __restrict__ test_x,
                 const float* __restrict__ train_x)
{
    // Transposed tiles: [k][m] / [k][n]; row stride 68 keeps float4 alignment
    __shared__ float As[D][68];
    __shared__ float Bs[D][68];
    __shared__ float hna[TM];    // 0.5*||a||^2
    __shared__ float hnb[TN];    // 0.5*||b||^2
    __shared__ float red[16][TM];

    const int tid = threadIdx.x;
    const int tx  = tid & 15;    // m-group (4 rows each)
    const int ty  = tid >> 4;    // n-group (4 cols each)
    const int m0  = blockIdx.x * TM;
    const int n0  = blockIdx.y * CHUNK;

    // Stage A (test tile), transposed. Global reads coalesced along k.
    #pragma unroll
    for (int i = tid; i < TM * D; i += 256) {
        int m = i >> 6, k = i & 63;
        As[k][m] = test_x[(m0 + m) * D + k];
    }
    __syncthreads();

    // Half-norms of A rows (deterministic serial sum per row)
    if (tid < TM) {
        float s = 0.f;
        #pragma unroll
        for (int k = 0; k < D; k++) { float v = As[k][tid]; s += v * v; }
        hna[tid] = 0.5f * s;
    }

    float accm[4] = {0.f, 0.f, 0.f, 0.f};   // per-thread sums over its n columns
    const float invv = 1.0f / VARV;

    for (int nt = 0; nt < CHUNK; nt += TN) {
        __syncthreads();   // previous tile fully consumed (also covers hna first iter)

        // Stage B (train tile), transposed
        #pragma unroll
        for (int i = tid; i < TN * D; i += 256) {
            int n = i >> 6, k = i & 63;
            Bs[k][n] = train_x[(n0 + nt + n) * D + k];
        }
        __syncthreads();

        if (tid < TN) {
            float s = 0.f;
            #pragma unroll
            for (int k = 0; k < D; k++) { float v = Bs[k][tid]; s += v * v; }
            hnb[tid] = 0.5f * s;
        }
        __syncthreads();

        // 4x4 register tile over (m, n); dot products over k
        float dot[4][4];
        #pragma unroll
        for (int i = 0; i < 4; i++)
            #pragma unroll
            for (int j = 0; j < 4; j++) dot[i][j] = 0.f;

        #pragma unroll
        for (int k = 0; k < D; k++) {
            float4 a4 = *(const float4*)&As[k][tx * 4];
            float4 b4 = *(const float4*)&Bs[k][ty * 4];
            float av[4] = {a4.x, a4.y, a4.z, a4.w};
            float bv[4] = {b4.x, b4.y, b4.z, b4.w};
            #pragma unroll
            for (int i = 0; i < 4; i++)
                #pragma unroll
                for (int j = 0; j < 4; j++)
                    dot[i][j] = fmaf(av[i], bv[j], dot[i][j]);
        }

        float4 ha4 = *(const float4*)&hna[tx * 4];
        float4 hb4 = *(const float4*)&hnb[ty * 4];
        float hav[4] = {ha4.x, ha4.y, ha4.z, ha4.w};
        float hbv[4] = {hb4.x, hb4.y, hb4.z, hb4.w};

        // exp(-(na+nb-2dot)/(2var)) == exp((dot - na/2 - nb/2)/var)
        #pragma unroll
        for (int i = 0; i < 4; i++) {
            #pragma unroll
            for (int j = 0; j < 4; j++) {
                float arg = (dot[i][j] - hav[i] - hbv[j]) * invv;
                accm[i] += __expf(arg);
            }
        }
    }

    __syncthreads();
    #pragma unroll
    for (int i = 0; i < 4; i++) red[ty][tx * 4 + i] = accm[i];
    __syncthreads();

    // Deterministic reduction across the 16 n-groups
    if (tid < TM) {
        float s = 0.f;
        #pragma unroll
        for (int j = 0; j < 16; j++) s += red[j][tid];
        g_scratch[blockIdx.y * MTOT + m0 + tid] = s;
    }
}

__global__ void kde_final(float* __restrict__ out)
{
    int m = blockIdx.x * 256 + threadIdx.x;
    if (m >= MTOT) return;
    float s = 0.f;
    #pragma unroll
    for (int j = 0; j < NSPLIT; j++) s += g_scratch[j * MTOT + m];
    // coef = 1/sqrt(2*pi*var); mean over NTRAIN
    float coef = rsqrtf(2.0f * CUDART_PI_F * VARV);
    out[m] = s * coef * (1.0f / (float)NTRAIN);
}

extern "C" void kernel_launch(void* const* d_in, const int* in_sizes, int n_in,
                              void* d_out, int out_size)
{
    const float* test_x  = (const float*)d_in[0];   // [4,256,64] -> [1024,64]
    const float* train_x = (const float*)d_in[1];   // [4096,64]
    float* out = (float*)d_out;                     // [4,256] -> [1024]

    dim3 grid(MTOT / TM, NSPLIT);   // (16,16) = 256 blocks, single wave
    kde_partial<<<grid, 256>>>(test_x, train_x);
    kde_final<<<MTOT / 256, 256>>>(out);
}